// round 1
// baseline (speedup 1.0000x reference)
#include <cuda_runtime.h>

// Problem dims
#define B_  2048
#define M_  128
#define D_  512
#define H_  512
#define KU_ 1024   // user-linear K (2*D)

// GEMM tiling
#define BM 128
#define BN 64
#define BK 16

// Scratch (device globals — no allocation allowed)
__device__ float g_mi[B_ * H_];   // img mean
__device__ float g_mt[B_ * H_];   // txt mean
__device__ float g_u [B_ * H_];   // user-linear output
__device__ float g_wr[H_ * H_];   // W_r_img + W_r_txt

// ---------------------------------------------------------------------------
// Kernel 0: Wr sum (elementwise, tiny)
// ---------------------------------------------------------------------------
__global__ void wsum_kernel(const float* __restrict__ wri,
                            const float* __restrict__ wrt) {
    int i = blockIdx.x * blockDim.x + threadIdx.x;  // float4 index
    float4 a = reinterpret_cast<const float4*>(wri)[i];
    float4 b = reinterpret_cast<const float4*>(wrt)[i];
    reinterpret_cast<float4*>(g_wr)[i] =
        make_float4(a.x + b.x, a.y + b.y, a.z + b.z, a.w + b.w);
}

// ---------------------------------------------------------------------------
// Kernel 1: per-batch mean over M nodes.  grid (B, 2), block 128.
// Each thread owns one float4 column chunk (H/4 = 128 float4 per row).
// ---------------------------------------------------------------------------
__global__ void mean_kernel(const float* __restrict__ img,
                            const float* __restrict__ txt) {
    const int b = blockIdx.x;
    const float* src = (blockIdx.y == 0) ? img : txt;
    float*       dst = (blockIdx.y == 0) ? g_mi : g_mt;

    const float4* p = reinterpret_cast<const float4*>(src)
                      + (size_t)b * (M_ * H_ / 4) + threadIdx.x;
    float4 acc = make_float4(0.f, 0.f, 0.f, 0.f);
#pragma unroll 8
    for (int m = 0; m < M_; m++) {
        float4 v = p[(size_t)m * (H_ / 4)];
        acc.x += v.x; acc.y += v.y; acc.z += v.z; acc.w += v.w;
    }
    const float s = 1.0f / (float)M_;
    reinterpret_cast<float4*>(dst)[(size_t)b * (H_ / 4) + threadIdx.x] =
        make_float4(acc.x * s, acc.y * s, acc.z * s, acc.w * s);
}

// ---------------------------------------------------------------------------
// Kernel 2: u = concat(it, ii) @ W_user^T + b_user     [2048, 512], K=1024
// 128x64 tile, BK=16, 256 threads, 8x4 micro-tile.
// ---------------------------------------------------------------------------
__global__ __launch_bounds__(256) void gemm_user(
    const float* __restrict__ it, const float* __restrict__ ii,
    const float* __restrict__ Wu, const float* __restrict__ bu)
{
    __shared__ float As[BK][BM + 4];   // row stride 132 floats = 528B (16B-mult)
    __shared__ float Ws[BK][BN + 4];   // row stride 68  floats = 272B (16B-mult)

    const int bm  = blockIdx.x * BM;
    const int bn  = blockIdx.y * BN;
    const int tid = threadIdx.x;
    const int tx  = tid & 15;     // n group (4 cols)
    const int ty  = tid >> 4;     // m group (8 rows)

    float acc[8][4];
#pragma unroll
    for (int i = 0; i < 8; i++)
#pragma unroll
        for (int j = 0; j < 4; j++) acc[i][j] = 0.f;

    for (int kt = 0; kt < KU_; kt += BK) {
        // A tile: 128 rows x 16 k  (feat = [it | ii], split at k=512, tile-aligned)
#pragma unroll
        for (int i = 0; i < 2; i++) {
            int idx = tid + i * 256;       // 0..511 float4 slots
            int row = idx >> 2;            // 0..127
            int cv  = (idx & 3) << 2;      // 0,4,8,12
            int k   = kt + cv;
            const float* src = (k < D_)
                ? (it + (size_t)(bm + row) * D_ + k)
                : (ii + (size_t)(bm + row) * D_ + (k - D_));
            float4 v = *reinterpret_cast<const float4*>(src);
            As[cv + 0][row] = v.x; As[cv + 1][row] = v.y;
            As[cv + 2][row] = v.z; As[cv + 3][row] = v.w;
        }
        // W tile: 64 rows (h) x 16 k
        {
            int row = tid >> 2;
            int cv  = (tid & 3) << 2;
            float4 v = *reinterpret_cast<const float4*>(
                Wu + (size_t)(bn + row) * KU_ + kt + cv);
            Ws[cv + 0][row] = v.x; Ws[cv + 1][row] = v.y;
            Ws[cv + 2][row] = v.z; Ws[cv + 3][row] = v.w;
        }
        __syncthreads();

#pragma unroll
        for (int kk = 0; kk < BK; kk++) {
            float a[8], w[4];
            *reinterpret_cast<float4*>(a)     = *reinterpret_cast<const float4*>(&As[kk][ty * 8]);
            *reinterpret_cast<float4*>(a + 4) = *reinterpret_cast<const float4*>(&As[kk][ty * 8 + 4]);
            *reinterpret_cast<float4*>(w)     = *reinterpret_cast<const float4*>(&Ws[kk][tx * 4]);
#pragma unroll
            for (int i = 0; i < 8; i++)
#pragma unroll
                for (int j = 0; j < 4; j++)
                    acc[i][j] = fmaf(a[i], w[j], acc[i][j]);
        }
        __syncthreads();
    }

    // epilogue: + b_user, store to g_u (float4 rows)
    float4 bb = *reinterpret_cast<const float4*>(bu + bn + tx * 4);
#pragma unroll
    for (int i = 0; i < 8; i++) {
        int r = bm + ty * 8 + i;
        float4 c = make_float4(acc[i][0] + bb.x, acc[i][1] + bb.y,
                               acc[i][2] + bb.z, acc[i][3] + bb.w);
        *reinterpret_cast<float4*>(g_u + (size_t)r * H_ + bn + tx * 4) = c;
    }
}

// ---------------------------------------------------------------------------
// Kernel 3: out = relu( mi@Wli^T + mt@Wlt^T + u@(Wri+Wrt)^T + bli + blt )
// Same tiling; 3 accumulation phases of K=512 each.
// ---------------------------------------------------------------------------
__global__ __launch_bounds__(256) void gemm_out(
    const float* __restrict__ Wli, const float* __restrict__ Wlt,
    const float* __restrict__ bli, const float* __restrict__ blt,
    float* __restrict__ out)
{
    __shared__ float As[BK][BM + 4];
    __shared__ float Ws[BK][BN + 4];

    const int bm  = blockIdx.x * BM;
    const int bn  = blockIdx.y * BN;
    const int tid = threadIdx.x;
    const int tx  = tid & 15;
    const int ty  = tid >> 4;

    float acc[8][4];
#pragma unroll
    for (int i = 0; i < 8; i++)
#pragma unroll
        for (int j = 0; j < 4; j++) acc[i][j] = 0.f;

    const float* Aph[3] = { g_mi, g_mt, g_u };
    const float* Wph[3] = { Wli,  Wlt,  g_wr };

    for (int ph = 0; ph < 3; ph++) {
        const float* A = Aph[ph];
        const float* W = Wph[ph];
        for (int kt = 0; kt < H_; kt += BK) {
#pragma unroll
            for (int i = 0; i < 2; i++) {
                int idx = tid + i * 256;
                int row = idx >> 2;
                int cv  = (idx & 3) << 2;
                float4 v = *reinterpret_cast<const float4*>(
                    A + (size_t)(bm + row) * H_ + kt + cv);
                As[cv + 0][row] = v.x; As[cv + 1][row] = v.y;
                As[cv + 2][row] = v.z; As[cv + 3][row] = v.w;
            }
            {
                int row = tid >> 2;
                int cv  = (tid & 3) << 2;
                float4 v = *reinterpret_cast<const float4*>(
                    W + (size_t)(bn + row) * H_ + kt + cv);
                Ws[cv + 0][row] = v.x; Ws[cv + 1][row] = v.y;
                Ws[cv + 2][row] = v.z; Ws[cv + 3][row] = v.w;
            }
            __syncthreads();

#pragma unroll
            for (int kk = 0; kk < BK; kk++) {
                float a[8], w[4];
                *reinterpret_cast<float4*>(a)     = *reinterpret_cast<const float4*>(&As[kk][ty * 8]);
                *reinterpret_cast<float4*>(a + 4) = *reinterpret_cast<const float4*>(&As[kk][ty * 8 + 4]);
                *reinterpret_cast<float4*>(w)     = *reinterpret_cast<const float4*>(&Ws[kk][tx * 4]);
#pragma unroll
                for (int i = 0; i < 8; i++)
#pragma unroll
                    for (int j = 0; j < 4; j++)
                        acc[i][j] = fmaf(a[i], w[j], acc[i][j]);
            }
            __syncthreads();
        }
    }

    // epilogue: + (bli + blt), ReLU, store
    float4 b1 = *reinterpret_cast<const float4*>(bli + bn + tx * 4);
    float4 b2 = *reinterpret_cast<const float4*>(blt + bn + tx * 4);
    float4 bb = make_float4(b1.x + b2.x, b1.y + b2.y, b1.z + b2.z, b1.w + b2.w);
#pragma unroll
    for (int i = 0; i < 8; i++) {
        int r = bm + ty * 8 + i;
        float4 c = make_float4(
            fmaxf(acc[i][0] + bb.x, 0.f),
            fmaxf(acc[i][1] + bb.y, 0.f),
            fmaxf(acc[i][2] + bb.z, 0.f),
            fmaxf(acc[i][3] + bb.w, 0.f));
        *reinterpret_cast<float4*>(out + (size_t)r * H_ + bn + tx * 4) = c;
    }
}

// ---------------------------------------------------------------------------
extern "C" void kernel_launch(void* const* d_in, const int* in_sizes, int n_in,
                              void* d_out, int out_size) {
    (void)in_sizes; (void)n_in; (void)out_size;
    const float* it  = (const float*)d_in[0];   // input_text        [B,1,D]
    const float* ii  = (const float*)d_in[1];   // input_img         [B,1,D]
    const float* btf = (const float*)d_in[2];   // base_text_features[B,M,H]
    const float* bif = (const float*)d_in[3];   // base_img_features [B,M,H]
    const float* Wu  = (const float*)d_in[4];   // [H, 2D]
    const float* bu  = (const float*)d_in[5];   // [H]
    const float* Wli = (const float*)d_in[6];   // [H, H]
    const float* bli = (const float*)d_in[7];   // [H]
    const float* Wri = (const float*)d_in[8];   // [H, H]
    const float* Wlt = (const float*)d_in[9];   // [H, H]
    const float* blt = (const float*)d_in[10];  // [H]
    const float* Wrt = (const float*)d_in[11];  // [H, H]
    float* out = (float*)d_out;

    wsum_kernel<<<(H_ * H_ / 4) / 256, 256>>>(Wri, Wrt);
    mean_kernel<<<dim3(B_, 2), 128>>>(bif, btf);
    gemm_user<<<dim3(B_ / BM, H_ / BN), 256>>>(it, ii, Wu, bu);
    gemm_out<<<dim3(B_ / BM, H_ / BN), 256>>>(Wli, Wlt, bli, blt, out);
}

// round 2
// speedup vs baseline: 1.0138x; 1.0138x over previous
#include <cuda_runtime.h>

// Problem dims
#define B_  2048
#define M_  128
#define D_  512
#define H_  512
#define KU_ 1024   // user-linear K (2*D)

// GEMM tiling
#define BM 128
#define BN 64
#define BK 16

typedef unsigned long long u64;

__device__ __forceinline__ void fma2(u64& d, u64 a, u64 b) {
    asm volatile("fma.rn.f32x2 %0, %1, %2, %0;" : "+l"(d) : "l"(a), "l"(b));
}
__device__ __forceinline__ float2 unpk(u64 v) {
    float2 r; asm("mov.b64 {%0,%1}, %2;" : "=f"(r.x), "=f"(r.y) : "l"(v)); return r;
}

// Scratch (device globals — no allocation allowed)
__device__ float g_mi[B_ * H_];   // img mean
__device__ float g_mt[B_ * H_];   // txt mean
__device__ float g_u [B_ * H_];   // user-linear output
__device__ float g_wr[H_ * H_];   // W_r_img + W_r_txt

// ---------------------------------------------------------------------------
// Kernel 0: Wr sum (elementwise, tiny)
// ---------------------------------------------------------------------------
__global__ void wsum_kernel(const float* __restrict__ wri,
                            const float* __restrict__ wrt) {
    int i = blockIdx.x * blockDim.x + threadIdx.x;
    float4 a = reinterpret_cast<const float4*>(wri)[i];
    float4 b = reinterpret_cast<const float4*>(wrt)[i];
    reinterpret_cast<float4*>(g_wr)[i] =
        make_float4(a.x + b.x, a.y + b.y, a.z + b.z, a.w + b.w);
}

// ---------------------------------------------------------------------------
// Kernel 1: per-batch mean over M nodes (HBM-roofline bound; keep simple)
// ---------------------------------------------------------------------------
__global__ void mean_kernel(const float* __restrict__ img,
                            const float* __restrict__ txt) {
    const int b = blockIdx.x;
    const float* src = (blockIdx.y == 0) ? img : txt;
    float*       dst = (blockIdx.y == 0) ? g_mi : g_mt;

    const float4* p = reinterpret_cast<const float4*>(src)
                      + (size_t)b * (M_ * H_ / 4) + threadIdx.x;
    float4 acc = make_float4(0.f, 0.f, 0.f, 0.f);
#pragma unroll 8
    for (int m = 0; m < M_; m++) {
        float4 v = p[(size_t)m * (H_ / 4)];
        acc.x += v.x; acc.y += v.y; acc.z += v.z; acc.w += v.w;
    }
    const float s = 1.0f / (float)M_;
    reinterpret_cast<float4*>(dst)[(size_t)b * (H_ / 4) + threadIdx.x] =
        make_float4(acc.x * s, acc.y * s, acc.z * s, acc.w * s);
}

// ---------------------------------------------------------------------------
// Shared GEMM machinery: 128x64 tile, BK=16, 256 threads, 8x4 micro-tile,
// f32x2 packed FMA (acc pairs over M), W duplicated in smem so B operand
// loads pre-packed. Double-buffered smem, register-staged prefetch.
// ---------------------------------------------------------------------------
#define AS_LD (BM + 4)        // 132 floats/row (528B, 16B-mult)
#define WS_LD (2 * BN + 8)    // 136 floats/row (544B, 16B-mult)

// ---------------------------------------------------------------------------
// Kernel 2: u = concat(it, ii) @ W_user^T + b_user   [2048,512] K=1024
// ---------------------------------------------------------------------------
__global__ __launch_bounds__(256) void gemm_user(
    const float* __restrict__ it, const float* __restrict__ ii,
    const float* __restrict__ Wu, const float* __restrict__ bu)
{
    __shared__ float As[2][BK][AS_LD];
    __shared__ float Ws[2][BK][WS_LD];

    const int bm  = blockIdx.x * BM;
    const int bn  = blockIdx.y * BN;
    const int tid = threadIdx.x;
    const int tx  = tid & 15;
    const int ty  = tid >> 4;

    // loader indices (constant over loop)
    const int ar0 = tid >> 2;            // A row for slot 0 (0..63)
    const int ar1 = ar0 + 64;            // A row for slot 1
    const int acv = (tid & 3) << 2;      // A k-offset within tile
    const int wrow = tid >> 2;           // W n row (0..63)
    const int wcv  = (tid & 3) << 2;     // W k-offset

    u64 acc2[4][4];
#pragma unroll
    for (int i = 0; i < 4; i++)
#pragma unroll
        for (int j = 0; j < 4; j++) acc2[i][j] = 0ull;

    const int NT = KU_ / BK;   // 64 tiles
    float4 av0, av1, wv;

    // prologue: load tile 0 into regs, store to buf 0
    {
        int k = acv;
        const float* s0 = (k < D_) ? (it + (size_t)(bm + ar0) * D_ + k)
                                   : (ii + (size_t)(bm + ar0) * D_ + (k - D_));
        const float* s1 = (k < D_) ? (it + (size_t)(bm + ar1) * D_ + k)
                                   : (ii + (size_t)(bm + ar1) * D_ + (k - D_));
        av0 = *reinterpret_cast<const float4*>(s0);
        av1 = *reinterpret_cast<const float4*>(s1);
        wv  = *reinterpret_cast<const float4*>(Wu + (size_t)(bn + wrow) * KU_ + wcv);
        As[0][acv+0][ar0] = av0.x; As[0][acv+1][ar0] = av0.y;
        As[0][acv+2][ar0] = av0.z; As[0][acv+3][ar0] = av0.w;
        As[0][acv+0][ar1] = av1.x; As[0][acv+1][ar1] = av1.y;
        As[0][acv+2][ar1] = av1.z; As[0][acv+3][ar1] = av1.w;
        Ws[0][wcv+0][2*wrow] = wv.x; Ws[0][wcv+0][2*wrow+1] = wv.x;
        Ws[0][wcv+1][2*wrow] = wv.y; Ws[0][wcv+1][2*wrow+1] = wv.y;
        Ws[0][wcv+2][2*wrow] = wv.z; Ws[0][wcv+2][2*wrow+1] = wv.z;
        Ws[0][wcv+3][2*wrow] = wv.w; Ws[0][wcv+3][2*wrow+1] = wv.w;
    }
    __syncthreads();

    int p = 0;
    for (int t = 0; t < NT; t++) {
        // prefetch tile t+1 into regs
        if (t + 1 < NT) {
            int kt = (t + 1) * BK;
            int k  = kt + acv;
            const float* s0 = (k < D_) ? (it + (size_t)(bm + ar0) * D_ + k)
                                       : (ii + (size_t)(bm + ar0) * D_ + (k - D_));
            const float* s1 = (k < D_) ? (it + (size_t)(bm + ar1) * D_ + k)
                                       : (ii + (size_t)(bm + ar1) * D_ + (k - D_));
            av0 = *reinterpret_cast<const float4*>(s0);
            av1 = *reinterpret_cast<const float4*>(s1);
            wv  = *reinterpret_cast<const float4*>(Wu + (size_t)(bn + wrow) * KU_ + kt + wcv);
        }
        // compute on buffer p
#pragma unroll
        for (int kk = 0; kk < BK; kk++) {
            const u64* ap = reinterpret_cast<const u64*>(&As[p][kk][ty * 8]);
            const u64* wp = reinterpret_cast<const u64*>(&Ws[p][kk][tx * 8]);
            u64 a2[4], w2[4];
            *reinterpret_cast<ulonglong2*>(a2)     = *reinterpret_cast<const ulonglong2*>(ap);
            *reinterpret_cast<ulonglong2*>(a2 + 2) = *reinterpret_cast<const ulonglong2*>(ap + 2);
            *reinterpret_cast<ulonglong2*>(w2)     = *reinterpret_cast<const ulonglong2*>(wp);
            *reinterpret_cast<ulonglong2*>(w2 + 2) = *reinterpret_cast<const ulonglong2*>(wp + 2);
#pragma unroll
            for (int j = 0; j < 4; j++)
#pragma unroll
                for (int i = 0; i < 4; i++)
                    fma2(acc2[i][j], a2[i], w2[j]);
        }
        // store prefetched regs to buffer p^1
        if (t + 1 < NT) {
            int q = p ^ 1;
            As[q][acv+0][ar0] = av0.x; As[q][acv+1][ar0] = av0.y;
            As[q][acv+2][ar0] = av0.z; As[q][acv+3][ar0] = av0.w;
            As[q][acv+0][ar1] = av1.x; As[q][acv+1][ar1] = av1.y;
            As[q][acv+2][ar1] = av1.z; As[q][acv+3][ar1] = av1.w;
            Ws[q][wcv+0][2*wrow] = wv.x; Ws[q][wcv+0][2*wrow+1] = wv.x;
            Ws[q][wcv+1][2*wrow] = wv.y; Ws[q][wcv+1][2*wrow+1] = wv.y;
            Ws[q][wcv+2][2*wrow] = wv.z; Ws[q][wcv+2][2*wrow+1] = wv.z;
            Ws[q][wcv+3][2*wrow] = wv.w; Ws[q][wcv+3][2*wrow+1] = wv.w;
        }
        __syncthreads();
        p ^= 1;
    }

    // epilogue: + b_user, store to g_u
    float4 bb = *reinterpret_cast<const float4*>(bu + bn + tx * 4);
#pragma unroll
    for (int i2 = 0; i2 < 4; i2++) {
        float2 c0 = unpk(acc2[i2][0]);
        float2 c1 = unpk(acc2[i2][1]);
        float2 c2 = unpk(acc2[i2][2]);
        float2 c3 = unpk(acc2[i2][3]);
        int rlo = bm + ty * 8 + 2 * i2;
        *reinterpret_cast<float4*>(g_u + (size_t)rlo * H_ + bn + tx * 4) =
            make_float4(c0.x + bb.x, c1.x + bb.y, c2.x + bb.z, c3.x + bb.w);
        *reinterpret_cast<float4*>(g_u + (size_t)(rlo + 1) * H_ + bn + tx * 4) =
            make_float4(c0.y + bb.x, c1.y + bb.y, c2.y + bb.z, c3.y + bb.w);
    }
}

// ---------------------------------------------------------------------------
// Kernel 3: out = relu( mi@Wli^T + mt@Wlt^T + u@(Wri+Wrt)^T + bli + blt )
// 3 phases of K=512 concatenated into one 96-tile pipelined loop.
// ---------------------------------------------------------------------------
__global__ __launch_bounds__(256) void gemm_out(
    const float* __restrict__ Wli, const float* __restrict__ Wlt,
    const float* __restrict__ bli, const float* __restrict__ blt,
    float* __restrict__ out)
{
    __shared__ float As[2][BK][AS_LD];
    __shared__ float Ws[2][BK][WS_LD];

    const int bm  = blockIdx.x * BM;
    const int bn  = blockIdx.y * BN;
    const int tid = threadIdx.x;
    const int tx  = tid & 15;
    const int ty  = tid >> 4;

    const int ar0 = tid >> 2;
    const int ar1 = ar0 + 64;
    const int acv = (tid & 3) << 2;
    const int wrow = tid >> 2;
    const int wcv  = (tid & 3) << 2;

    const float* Aph[3] = { g_mi, g_mt, g_u };
    const float* Wph[3] = { Wli,  Wlt,  g_wr };

    u64 acc2[4][4];
#pragma unroll
    for (int i = 0; i < 4; i++)
#pragma unroll
        for (int j = 0; j < 4; j++) acc2[i][j] = 0ull;

    const int NT = 3 * (H_ / BK);   // 96 tiles
    float4 av0, av1, wv;

    {
        const float* A = Aph[0];
        const float* W = Wph[0];
        av0 = *reinterpret_cast<const float4*>(A + (size_t)(bm + ar0) * H_ + acv);
        av1 = *reinterpret_cast<const float4*>(A + (size_t)(bm + ar1) * H_ + acv);
        wv  = *reinterpret_cast<const float4*>(W + (size_t)(bn + wrow) * H_ + wcv);
        As[0][acv+0][ar0] = av0.x; As[0][acv+1][ar0] = av0.y;
        As[0][acv+2][ar0] = av0.z; As[0][acv+3][ar0] = av0.w;
        As[0][acv+0][ar1] = av1.x; As[0][acv+1][ar1] = av1.y;
        As[0][acv+2][ar1] = av1.z; As[0][acv+3][ar1] = av1.w;
        Ws[0][wcv+0][2*wrow] = wv.x; Ws[0][wcv+0][2*wrow+1] = wv.x;
        Ws[0][wcv+1][2*wrow] = wv.y; Ws[0][wcv+1][2*wrow+1] = wv.y;
        Ws[0][wcv+2][2*wrow] = wv.z; Ws[0][wcv+2][2*wrow+1] = wv.z;
        Ws[0][wcv+3][2*wrow] = wv.w; Ws[0][wcv+3][2*wrow+1] = wv.w;
    }
    __syncthreads();

    int p = 0;
    for (int t = 0; t < NT; t++) {
        if (t + 1 < NT) {
            int tn = t + 1;
            int ph = tn >> 5;            // 32 tiles per 512-K phase
            int kt = (tn & 31) * BK;
            const float* A = Aph[ph];
            const float* W = Wph[ph];
            av0 = *reinterpret_cast<const float4*>(A + (size_t)(bm + ar0) * H_ + kt + acv);
            av1 = *reinterpret_cast<const float4*>(A + (size_t)(bm + ar1) * H_ + kt + acv);
            wv  = *reinterpret_cast<const float4*>(W + (size_t)(bn + wrow) * H_ + kt + wcv);
        }
#pragma unroll
        for (int kk = 0; kk < BK; kk++) {
            const u64* ap = reinterpret_cast<const u64*>(&As[p][kk][ty * 8]);
            const u64* wp = reinterpret_cast<const u64*>(&Ws[p][kk][tx * 8]);
            u64 a2[4], w2[4];
            *reinterpret_cast<ulonglong2*>(a2)     = *reinterpret_cast<const ulonglong2*>(ap);
            *reinterpret_cast<ulonglong2*>(a2 + 2) = *reinterpret_cast<const ulonglong2*>(ap + 2);
            *reinterpret_cast<ulonglong2*>(w2)     = *reinterpret_cast<const ulonglong2*>(wp);
            *reinterpret_cast<ulonglong2*>(w2 + 2) = *reinterpret_cast<const ulonglong2*>(wp + 2);
#pragma unroll
            for (int j = 0; j < 4; j++)
#pragma unroll
                for (int i = 0; i < 4; i++)
                    fma2(acc2[i][j], a2[i], w2[j]);
        }
        if (t + 1 < NT) {
            int q = p ^ 1;
            As[q][acv+0][ar0] = av0.x; As[q][acv+1][ar0] = av0.y;
            As[q][acv+2][ar0] = av0.z; As[q][acv+3][ar0] = av0.w;
            As[q][acv+0][ar1] = av1.x; As[q][acv+1][ar1] = av1.y;
            As[q][acv+2][ar1] = av1.z; As[q][acv+3][ar1] = av1.w;
            Ws[q][wcv+0][2*wrow] = wv.x; Ws[q][wcv+0][2*wrow+1] = wv.x;
            Ws[q][wcv+1][2*wrow] = wv.y; Ws[q][wcv+1][2*wrow+1] = wv.y;
            Ws[q][wcv+2][2*wrow] = wv.z; Ws[q][wcv+2][2*wrow+1] = wv.z;
            Ws[q][wcv+3][2*wrow] = wv.w; Ws[q][wcv+3][2*wrow+1] = wv.w;
        }
        __syncthreads();
        p ^= 1;
    }

    // epilogue: + (bli + blt), ReLU, store
    float4 b1 = *reinterpret_cast<const float4*>(bli + bn + tx * 4);
    float4 b2 = *reinterpret_cast<const float4*>(blt + bn + tx * 4);
    float4 bb = make_float4(b1.x + b2.x, b1.y + b2.y, b1.z + b2.z, b1.w + b2.w);
#pragma unroll
    for (int i2 = 0; i2 < 4; i2++) {
        float2 c0 = unpk(acc2[i2][0]);
        float2 c1 = unpk(acc2[i2][1]);
        float2 c2 = unpk(acc2[i2][2]);
        float2 c3 = unpk(acc2[i2][3]);
        int rlo = bm + ty * 8 + 2 * i2;
        *reinterpret_cast<float4*>(out + (size_t)rlo * H_ + bn + tx * 4) =
            make_float4(fmaxf(c0.x + bb.x, 0.f), fmaxf(c1.x + bb.y, 0.f),
                        fmaxf(c2.x + bb.z, 0.f), fmaxf(c3.x + bb.w, 0.f));
        *reinterpret_cast<float4*>(out + (size_t)(rlo + 1) * H_ + bn + tx * 4) =
            make_float4(fmaxf(c0.y + bb.x, 0.f), fmaxf(c1.y + bb.y, 0.f),
                        fmaxf(c2.y + bb.z, 0.f), fmaxf(c3.y + bb.w, 0.f));
    }
}

// ---------------------------------------------------------------------------
extern "C" void kernel_launch(void* const* d_in, const int* in_sizes, int n_in,
                              void* d_out, int out_size) {
    (void)in_sizes; (void)n_in; (void)out_size;
    const float* it  = (const float*)d_in[0];
    const float* ii  = (const float*)d_in[1];
    const float* btf = (const float*)d_in[2];
    const float* bif = (const float*)d_in[3];
    const float* Wu  = (const float*)d_in[4];
    const float* bu  = (const float*)d_in[5];
    const float* Wli = (const float*)d_in[6];
    const float* bli = (const float*)d_in[7];
    const float* Wri = (const float*)d_in[8];
    const float* Wlt = (const float*)d_in[9];
    const float* blt = (const float*)d_in[10];
    const float* Wrt = (const float*)d_in[11];
    float* out = (float*)d_out;

    wsum_kernel<<<(H_ * H_ / 4) / 256, 256>>>(Wri, Wrt);
    mean_kernel<<<dim3(B_, 2), 128>>>(bif, btf);
    gemm_user<<<dim3(B_ / BM, H_ / BN), 256>>>(it, ii, Wu, bu);
    gemm_out<<<dim3(B_ / BM, H_ / BN), 256>>>(Wli, Wlt, bli, blt, out);
}

// round 3
// speedup vs baseline: 1.0912x; 1.0764x over previous
#include <cuda_runtime.h>

// Problem dims
#define B_  2048
#define M_  128
#define D_  512
#define H_  512
#define KU_ 1024   // user-linear K (2*D)

// GEMM tiling
#define BM 128
#define BN 64
#define BK 16
#define AS_LD (BM + 4)        // 132 floats/row
#define WS_LD (2 * BN + 8)    // 136 floats/row (W duplicated for packed B operand)

typedef unsigned long long u64;

__device__ __forceinline__ void fma2(u64& d, u64 a, u64 b) {
    asm volatile("fma.rn.f32x2 %0, %1, %2, %0;" : "+l"(d) : "l"(a), "l"(b));
}
__device__ __forceinline__ float2 unpk(u64 v) {
    float2 r; asm("mov.b64 {%0,%1}, %2;" : "=f"(r.x), "=f"(r.y) : "l"(v)); return r;
}

// Scratch (device globals — no allocation allowed)
__device__ float g_mi[B_ * H_];   // img mean
__device__ float g_mt[B_ * H_];   // txt mean
__device__ float g_u [B_ * H_];   // user-linear output
__device__ float g_wr[H_ * H_];   // W_r_img + W_r_txt

// ---------------------------------------------------------------------------
// GEMM micro-kernel helpers (shared by both GEMMs)
// ---------------------------------------------------------------------------
__device__ __forceinline__ void load_frag(
    u64* a2, u64* w2,
    const float (*As)[AS_LD], const float (*Ws)[WS_LD],
    int kk, int ty, int tx)
{
    const u64* ap = reinterpret_cast<const u64*>(&As[kk][ty * 8]);
    const u64* wp = reinterpret_cast<const u64*>(&Ws[kk][tx * 8]);
    ulonglong2 t0 = *reinterpret_cast<const ulonglong2*>(ap);
    ulonglong2 t1 = *reinterpret_cast<const ulonglong2*>(ap + 2);
    a2[0] = t0.x; a2[1] = t0.y; a2[2] = t1.x; a2[3] = t1.y;
    ulonglong2 s0 = *reinterpret_cast<const ulonglong2*>(wp);
    ulonglong2 s1 = *reinterpret_cast<const ulonglong2*>(wp + 2);
    w2[0] = s0.x; w2[1] = s0.y; w2[2] = s1.x; w2[3] = s1.y;
}

__device__ __forceinline__ void mma_step(u64 acc2[4][4], const u64* a2, const u64* w2) {
#pragma unroll
    for (int j = 0; j < 4; j++)
#pragma unroll
        for (int i = 0; i < 4; i++)
            fma2(acc2[i][j], a2[i], w2[j]);
}

// Compute one BK-deep tile on smem buffer p with operand double-buffering.
__device__ __forceinline__ void tile_compute(
    u64 acc2[4][4],
    const float (*As)[AS_LD], const float (*Ws)[WS_LD],
    int ty, int tx)
{
    u64 a2[2][4], w2[2][4];
    load_frag(a2[0], w2[0], As, Ws, 0, ty, tx);
#pragma unroll
    for (int kk = 0; kk < BK; kk++) {
        int cur = kk & 1;
        if (kk + 1 < BK)
            load_frag(a2[cur ^ 1], w2[cur ^ 1], As, Ws, kk + 1, ty, tx);
        mma_step(acc2, a2[cur], w2[cur]);
    }
}

__device__ __forceinline__ void store_tile(
    float As[BK][AS_LD], float Ws[BK][WS_LD],
    const float4& av0, const float4& av1, const float4& wv,
    int ar0, int ar1, int acv, int wrow, int wcv)
{
    As[acv + 0][ar0] = av0.x; As[acv + 1][ar0] = av0.y;
    As[acv + 2][ar0] = av0.z; As[acv + 3][ar0] = av0.w;
    As[acv + 0][ar1] = av1.x; As[acv + 1][ar1] = av1.y;
    As[acv + 2][ar1] = av1.z; As[acv + 3][ar1] = av1.w;
    Ws[wcv + 0][2 * wrow] = wv.x; Ws[wcv + 0][2 * wrow + 1] = wv.x;
    Ws[wcv + 1][2 * wrow] = wv.y; Ws[wcv + 1][2 * wrow + 1] = wv.y;
    Ws[wcv + 2][2 * wrow] = wv.z; Ws[wcv + 2][2 * wrow + 1] = wv.z;
    Ws[wcv + 3][2 * wrow] = wv.w; Ws[wcv + 3][2 * wrow + 1] = wv.w;
}

// ---------------------------------------------------------------------------
// Kernel 1 (fused): blocks [0,128)   -> gemm_user tiles
//                   blocks [128,2176)-> per-batch means (2 rows per block)
//                   blocks [2176,2432)-> wsum
// gemm blocks go first so they occupy distinct SMs in wave 1; DRAM-bound mean
// blocks overlap with the FMA-bound GEMM.
// ---------------------------------------------------------------------------
__global__ __launch_bounds__(256) void fused_prep(
    const float* __restrict__ it, const float* __restrict__ ii,
    const float* __restrict__ Wu, const float* __restrict__ bu,
    const float* __restrict__ img, const float* __restrict__ txt,
    const float* __restrict__ wri, const float* __restrict__ wrt)
{
    __shared__ float As[2][BK][AS_LD];
    __shared__ float Ws[2][BK][WS_LD];

    const int bid = blockIdx.x;
    const int tid = threadIdx.x;

    if (bid >= 2176) {
        // ---- wsum: g_wr = Wri + Wrt ----
        int i = (bid - 2176) * 256 + tid;
        float4 a = reinterpret_cast<const float4*>(wri)[i];
        float4 b = reinterpret_cast<const float4*>(wrt)[i];
        reinterpret_cast<float4*>(g_wr)[i] =
            make_float4(a.x + b.x, a.y + b.y, a.z + b.z, a.w + b.w);
        return;
    }

    if (bid >= 128) {
        // ---- mean over M nodes: block handles 2 batch rows of one modality ----
        int p    = bid - 128;
        int modal = p >> 10;               // 0: img, 1: txt
        int b    = (p & 1023) * 2 + (tid >> 7);
        int col  = tid & 127;
        const float* src = modal ? txt : img;
        float*       dst = modal ? g_mt : g_mi;

        const float4* q = reinterpret_cast<const float4*>(src)
                          + (size_t)b * (M_ * H_ / 4) + col;
        float4 acc = make_float4(0.f, 0.f, 0.f, 0.f);
#pragma unroll 8
        for (int m = 0; m < M_; m++) {
            float4 v = q[(size_t)m * (H_ / 4)];
            acc.x += v.x; acc.y += v.y; acc.z += v.z; acc.w += v.w;
        }
        const float s = 1.0f / (float)M_;
        reinterpret_cast<float4*>(dst)[(size_t)b * (H_ / 4) + col] =
            make_float4(acc.x * s, acc.y * s, acc.z * s, acc.w * s);
        return;
    }

    // ---- gemm_user: u = concat(it, ii) @ Wu^T + bu ----
    const int bm  = (bid >> 3) * BM;      // 16 m-tiles
    const int bn  = (bid & 7) * BN;       // 8 n-tiles
    const int tx  = tid & 15;
    const int ty  = tid >> 4;

    const int ar0 = tid >> 2;
    const int ar1 = ar0 + 64;
    const int acv = (tid & 3) << 2;
    const int wrow = tid >> 2;
    const int wcv  = (tid & 3) << 2;

    u64 acc2[4][4];
#pragma unroll
    for (int i = 0; i < 4; i++)
#pragma unroll
        for (int j = 0; j < 4; j++) acc2[i][j] = 0ull;

    const int NT = KU_ / BK;   // 64 tiles
    float4 av0, av1, wv;

    {
        int k = acv;
        const float* s0 = (k < D_) ? (it + (size_t)(bm + ar0) * D_ + k)
                                   : (ii + (size_t)(bm + ar0) * D_ + (k - D_));
        const float* s1 = (k < D_) ? (it + (size_t)(bm + ar1) * D_ + k)
                                   : (ii + (size_t)(bm + ar1) * D_ + (k - D_));
        av0 = *reinterpret_cast<const float4*>(s0);
        av1 = *reinterpret_cast<const float4*>(s1);
        wv  = *reinterpret_cast<const float4*>(Wu + (size_t)(bn + wrow) * KU_ + wcv);
        store_tile(As[0], Ws[0], av0, av1, wv, ar0, ar1, acv, wrow, wcv);
    }
    __syncthreads();

    int p = 0;
    for (int t = 0; t < NT; t++) {
        if (t + 1 < NT) {
            int kt = (t + 1) * BK;
            int k  = kt + acv;
            const float* s0 = (k < D_) ? (it + (size_t)(bm + ar0) * D_ + k)
                                       : (ii + (size_t)(bm + ar0) * D_ + (k - D_));
            const float* s1 = (k < D_) ? (it + (size_t)(bm + ar1) * D_ + k)
                                       : (ii + (size_t)(bm + ar1) * D_ + (k - D_));
            av0 = *reinterpret_cast<const float4*>(s0);
            av1 = *reinterpret_cast<const float4*>(s1);
            wv  = *reinterpret_cast<const float4*>(Wu + (size_t)(bn + wrow) * KU_ + kt + wcv);
        }
        tile_compute(acc2, As[p], Ws[p], ty, tx);
        if (t + 1 < NT)
            store_tile(As[p ^ 1], Ws[p ^ 1], av0, av1, wv, ar0, ar1, acv, wrow, wcv);
        __syncthreads();
        p ^= 1;
    }

    float4 bb = *reinterpret_cast<const float4*>(bu + bn + tx * 4);
#pragma unroll
    for (int i2 = 0; i2 < 4; i2++) {
        float2 c0 = unpk(acc2[i2][0]);
        float2 c1 = unpk(acc2[i2][1]);
        float2 c2 = unpk(acc2[i2][2]);
        float2 c3 = unpk(acc2[i2][3]);
        int rlo = bm + ty * 8 + 2 * i2;
        *reinterpret_cast<float4*>(g_u + (size_t)rlo * H_ + bn + tx * 4) =
            make_float4(c0.x + bb.x, c1.x + bb.y, c2.x + bb.z, c3.x + bb.w);
        *reinterpret_cast<float4*>(g_u + (size_t)(rlo + 1) * H_ + bn + tx * 4) =
            make_float4(c0.y + bb.x, c1.y + bb.y, c2.y + bb.z, c3.y + bb.w);
    }
}

// ---------------------------------------------------------------------------
// Kernel 2: out = relu( mi@Wli^T + mt@Wlt^T + u@(Wri+Wrt)^T + bli + blt )
// 3 K=512 phases in one 96-tile pipelined loop, operand double-buffered.
// ---------------------------------------------------------------------------
__global__ __launch_bounds__(256) void gemm_out(
    const float* __restrict__ Wli, const float* __restrict__ Wlt,
    const float* __restrict__ bli, const float* __restrict__ blt,
    float* __restrict__ out)
{
    __shared__ float As[2][BK][AS_LD];
    __shared__ float Ws[2][BK][WS_LD];

    const int bm  = blockIdx.x * BM;
    const int bn  = blockIdx.y * BN;
    const int tid = threadIdx.x;
    const int tx  = tid & 15;
    const int ty  = tid >> 4;

    const int ar0 = tid >> 2;
    const int ar1 = ar0 + 64;
    const int acv = (tid & 3) << 2;
    const int wrow = tid >> 2;
    const int wcv  = (tid & 3) << 2;

    const float* Aph[3] = { g_mi, g_mt, g_u };
    const float* Wph[3] = { Wli,  Wlt,  g_wr };

    u64 acc2[4][4];
#pragma unroll
    for (int i = 0; i < 4; i++)
#pragma unroll
        for (int j = 0; j < 4; j++) acc2[i][j] = 0ull;

    const int NT = 3 * (H_ / BK);   // 96 tiles
    float4 av0, av1, wv;

    {
        const float* A = Aph[0];
        const float* W = Wph[0];
        av0 = *reinterpret_cast<const float4*>(A + (size_t)(bm + ar0) * H_ + acv);
        av1 = *reinterpret_cast<const float4*>(A + (size_t)(bm + ar1) * H_ + acv);
        wv  = *reinterpret_cast<const float4*>(W + (size_t)(bn + wrow) * H_ + wcv);
        store_tile(As[0], Ws[0], av0, av1, wv, ar0, ar1, acv, wrow, wcv);
    }
    __syncthreads();

    int p = 0;
    for (int t = 0; t < NT; t++) {
        if (t + 1 < NT) {
            int tn = t + 1;
            int ph = tn >> 5;            // 32 tiles per 512-K phase
            int kt = (tn & 31) * BK;
            const float* A = Aph[ph];
            const float* W = Wph[ph];
            av0 = *reinterpret_cast<const float4*>(A + (size_t)(bm + ar0) * H_ + kt + acv);
            av1 = *reinterpret_cast<const float4*>(A + (size_t)(bm + ar1) * H_ + kt + acv);
            wv  = *reinterpret_cast<const float4*>(W + (size_t)(bn + wrow) * H_ + kt + wcv);
        }
        tile_compute(acc2, As[p], Ws[p], ty, tx);
        if (t + 1 < NT)
            store_tile(As[p ^ 1], Ws[p ^ 1], av0, av1, wv, ar0, ar1, acv, wrow, wcv);
        __syncthreads();
        p ^= 1;
    }

    float4 b1 = *reinterpret_cast<const float4*>(bli + bn + tx * 4);
    float4 b2 = *reinterpret_cast<const float4*>(blt + bn + tx * 4);
    float4 bb = make_float4(b1.x + b2.x, b1.y + b2.y, b1.z + b2.z, b1.w + b2.w);
#pragma unroll
    for (int i2 = 0; i2 < 4; i2++) {
        float2 c0 = unpk(acc2[i2][0]);
        float2 c1 = unpk(acc2[i2][1]);
        float2 c2 = unpk(acc2[i2][2]);
        float2 c3 = unpk(acc2[i2][3]);
        int rlo = bm + ty * 8 + 2 * i2;
        *reinterpret_cast<float4*>(out + (size_t)rlo * H_ + bn + tx * 4) =
            make_float4(fmaxf(c0.x + bb.x, 0.f), fmaxf(c1.x + bb.y, 0.f),
                        fmaxf(c2.x + bb.z, 0.f), fmaxf(c3.x + bb.w, 0.f));
        *reinterpret_cast<float4*>(out + (size_t)(rlo + 1) * H_ + bn + tx * 4) =
            make_float4(fmaxf(c0.y + bb.x, 0.f), fmaxf(c1.y + bb.y, 0.f),
                        fmaxf(c2.y + bb.z, 0.f), fmaxf(c3.y + bb.w, 0.f));
    }
}

// ---------------------------------------------------------------------------
extern "C" void kernel_launch(void* const* d_in, const int* in_sizes, int n_in,
                              void* d_out, int out_size) {
    (void)in_sizes; (void)n_in; (void)out_size;
    const float* it  = (const float*)d_in[0];
    const float* ii  = (const float*)d_in[1];
    const float* btf = (const float*)d_in[2];
    const float* bif = (const float*)d_in[3];
    const float* Wu  = (const float*)d_in[4];
    const float* bu  = (const float*)d_in[5];
    const float* Wli = (const float*)d_in[6];
    const float* bli = (const float*)d_in[7];
    const float* Wri = (const float*)d_in[8];
    const float* Wlt = (const float*)d_in[9];
    const float* blt = (const float*)d_in[10];
    const float* Wrt = (const float*)d_in[11];
    float* out = (float*)d_out;

    fused_prep<<<2432, 256>>>(it, ii, Wu, bu, bif, btf, Wri, Wrt);
    gemm_out<<<dim3(B_ / BM, H_ / BN), 256>>>(Wli, Wlt, bli, blt, out);
}

// round 5
// speedup vs baseline: 1.2641x; 1.1584x over previous
#include <cuda_runtime.h>

// Problem dims
#define B_  2048
#define M_  128
#define D_  512
#define H_  512
#define KU_ 1024   // user-linear K (2*D)

// GEMM tiling: 128x64 tile, BK=16, 512 threads, 4Mx4N micro-tile, N-packed f32x2
#define BM 128
#define BN 64
#define BK 16
#define AS2_LD (2 * BM + 8)   // 264 floats/row: A duplicated (a,a) pairs
#define WS_LD  (BN + 4)       // 68 floats/row: W natural layout

typedef unsigned long long u64;

__device__ __forceinline__ void fma2(u64& d, u64 a, u64 b) {
    asm volatile("fma.rn.f32x2 %0, %1, %2, %0;" : "+l"(d) : "l"(a), "l"(b));
}
__device__ __forceinline__ float2 unpk(u64 v) {
    float2 r; asm("mov.b64 {%0,%1}, %2;" : "=f"(r.x), "=f"(r.y) : "l"(v)); return r;
}

// Scratch (device globals — no allocation allowed)
__device__ float g_mi[B_ * H_];   // img mean
__device__ float g_mt[B_ * H_];   // txt mean
__device__ float g_u [B_ * H_];   // user-linear output
__device__ float g_wr[H_ * H_];   // W_r_img + W_r_txt

// ---------------------------------------------------------------------------
// Store one float4 of A into smem as duplicated (v,v) pairs (STS.64 x4).
// ---------------------------------------------------------------------------
__device__ __forceinline__ void store_a_dup(float (*As2)[AS2_LD],
                                            const float4& v, int row, int cv) {
    *reinterpret_cast<float2*>(&As2[cv + 0][2 * row]) = make_float2(v.x, v.x);
    *reinterpret_cast<float2*>(&As2[cv + 1][2 * row]) = make_float2(v.y, v.y);
    *reinterpret_cast<float2*>(&As2[cv + 2][2 * row]) = make_float2(v.z, v.z);
    *reinterpret_cast<float2*>(&As2[cv + 3][2 * row]) = make_float2(v.w, v.w);
}
__device__ __forceinline__ void store_w(float (*Ws)[WS_LD],
                                        const float4& v, int row, int cv) {
    Ws[cv + 0][row] = v.x; Ws[cv + 1][row] = v.y;
    Ws[cv + 2][row] = v.z; Ws[cv + 3][row] = v.w;
}

// Compute one BK-deep tile. ty: 4-row m-group (0..31), tx: 4-col n-group (0..15).
__device__ __forceinline__ void tile_compute(
    u64 acc2[4][2],
    const float (*As2)[AS2_LD], const float (*Ws)[WS_LD],
    int ty, int tx)
{
#pragma unroll
    for (int kk = 0; kk < BK; kk++) {
        const u64* ap = reinterpret_cast<const u64*>(&As2[kk][ty * 8]);
        ulonglong2 t0 = *reinterpret_cast<const ulonglong2*>(ap);
        ulonglong2 t1 = *reinterpret_cast<const ulonglong2*>(ap + 2);
        ulonglong2 wv = *reinterpret_cast<const ulonglong2*>(&Ws[kk][tx * 4]);
        u64 a0 = t0.x, a1 = t0.y, a2 = t1.x, a3 = t1.y;
        u64 w0 = wv.x, w1 = wv.y;
        fma2(acc2[0][0], a0, w0); fma2(acc2[0][1], a0, w1);
        fma2(acc2[1][0], a1, w0); fma2(acc2[1][1], a1, w1);
        fma2(acc2[2][0], a2, w0); fma2(acc2[2][1], a2, w1);
        fma2(acc2[3][0], a3, w0); fma2(acc2[3][1], a3, w1);
    }
}

// ---------------------------------------------------------------------------
// Kernel 1 (fused, 512 threads):
//   blocks [0,128)      -> gemm_user tiles (16 m x 8 n)
//   blocks [128,1152)   -> per-batch means (4 batch rows per block)
//   blocks [1152,1280)  -> wsum
// ---------------------------------------------------------------------------
__global__ __launch_bounds__(512) void fused_prep(
    const float* __restrict__ it, const float* __restrict__ ii,
    const float* __restrict__ Wu, const float* __restrict__ bu,
    const float* __restrict__ img, const float* __restrict__ txt,
    const float* __restrict__ wri, const float* __restrict__ wrt)
{
    __shared__ float As2[2][BK][AS2_LD];
    __shared__ float Ws [2][BK][WS_LD];

    const int bid = blockIdx.x;
    const int tid = threadIdx.x;

    if (bid >= 1152) {
        // ---- wsum: g_wr = Wri + Wrt ----
        int i = (bid - 1152) * 512 + tid;
        float4 a = reinterpret_cast<const float4*>(wri)[i];
        float4 b = reinterpret_cast<const float4*>(wrt)[i];
        reinterpret_cast<float4*>(g_wr)[i] =
            make_float4(a.x + b.x, a.y + b.y, a.z + b.z, a.w + b.w);
        return;
    }

    if (bid >= 128) {
        // ---- mean over M nodes: block handles 4 batch rows of one modality ----
        int p     = bid - 128;            // 0..1023
        int modal = p >> 9;               // 0: img, 1: txt
        int b     = (p & 511) * 4 + (tid >> 7);
        int col   = tid & 127;
        const float* src = modal ? txt : img;
        float*       dst = modal ? g_mt : g_mi;

        const float4* q = reinterpret_cast<const float4*>(src)
                          + (size_t)b * (M_ * H_ / 4) + col;
        float4 acc = make_float4(0.f, 0.f, 0.f, 0.f);
#pragma unroll 8
        for (int m = 0; m < M_; m++) {
            float4 v = q[(size_t)m * (H_ / 4)];
            acc.x += v.x; acc.y += v.y; acc.z += v.z; acc.w += v.w;
        }
        const float s = 1.0f / (float)M_;
        reinterpret_cast<float4*>(dst)[(size_t)b * (H_ / 4) + col] =
            make_float4(acc.x * s, acc.y * s, acc.z * s, acc.w * s);
        return;
    }

    // ---- gemm_user: u = concat(it, ii) @ Wu^T + bu ----
    const int bm = (bid >> 3) * BM;
    const int bn = (bid & 7) * BN;
    const int tx = tid & 15;          // n-group (4 cols)
    const int ty = tid >> 4;          // m-group (4 rows)

    const int arow = tid >> 2;        // A loader: 0..127
    const int acv  = (tid & 3) << 2;
    const int wrow = tid >> 2;        // W loader (tid<256): 0..63
    const int wcv  = (tid & 3) << 2;

    u64 acc2[4][2];
#pragma unroll
    for (int i = 0; i < 4; i++) { acc2[i][0] = 0ull; acc2[i][1] = 0ull; }

    const int NT = KU_ / BK;   // 64 tiles
    float4 av, wv;

    {
        int k = acv;
        const float* s0 = (k < D_) ? (it + (size_t)(bm + arow) * D_ + k)
                                   : (ii + (size_t)(bm + arow) * D_ + (k - D_));
        av = *reinterpret_cast<const float4*>(s0);
        store_a_dup(As2[0], av, arow, acv);
        if (tid < 256) {
            wv = *reinterpret_cast<const float4*>(Wu + (size_t)(bn + wrow) * KU_ + wcv);
            store_w(Ws[0], wv, wrow, wcv);
        }
    }
    __syncthreads();

    int p = 0;
    for (int t = 0; t < NT; t++) {
        if (t + 1 < NT) {
            int kt = (t + 1) * BK;
            int k  = kt + acv;
            const float* s0 = (k < D_) ? (it + (size_t)(bm + arow) * D_ + k)
                                       : (ii + (size_t)(bm + arow) * D_ + (k - D_));
            av = *reinterpret_cast<const float4*>(s0);
            if (tid < 256)
                wv = *reinterpret_cast<const float4*>(Wu + (size_t)(bn + wrow) * KU_ + kt + wcv);
        }
        tile_compute(acc2, As2[p], Ws[p], ty, tx);
        if (t + 1 < NT) {
            store_a_dup(As2[p ^ 1], av, arow, acv);
            if (tid < 256) store_w(Ws[p ^ 1], wv, wrow, wcv);
        }
        __syncthreads();
        p ^= 1;
    }

    float4 bb = *reinterpret_cast<const float4*>(bu + bn + tx * 4);
#pragma unroll
    for (int i = 0; i < 4; i++) {
        float2 c0 = unpk(acc2[i][0]);   // (n0, n1)
        float2 c1 = unpk(acc2[i][1]);   // (n2, n3)
        int r = bm + ty * 4 + i;
        *reinterpret_cast<float4*>(g_u + (size_t)r * H_ + bn + tx * 4) =
            make_float4(c0.x + bb.x, c0.y + bb.y, c1.x + bb.z, c1.y + bb.w);
    }
}

// ---------------------------------------------------------------------------
// Kernel 2: out = relu( mi@Wli^T + mt@Wlt^T + u@(Wri+Wrt)^T + bli + blt )
// 3 K=512 phases in one 96-tile pipelined loop. 512 threads.
// ---------------------------------------------------------------------------
__global__ __launch_bounds__(512) void gemm_out(
    const float* __restrict__ Wli, const float* __restrict__ Wlt,
    const float* __restrict__ bli, const float* __restrict__ blt,
    float* __restrict__ out)
{
    __shared__ float As2[2][BK][AS2_LD];
    __shared__ float Ws [2][BK][WS_LD];

    const int bm  = blockIdx.x * BM;
    const int bn  = blockIdx.y * BN;
    const int tid = threadIdx.x;
    const int tx  = tid & 15;
    const int ty  = tid >> 4;

    const int arow = tid >> 2;
    const int acv  = (tid & 3) << 2;
    const int wrow = tid >> 2;
    const int wcv  = (tid & 3) << 2;

    const float* Aph[3] = { g_mi, g_mt, g_u };
    const float* Wph[3] = { Wli,  Wlt,  g_wr };

    u64 acc2[4][2];
#pragma unroll
    for (int i = 0; i < 4; i++) { acc2[i][0] = 0ull; acc2[i][1] = 0ull; }

    const int NT = 3 * (H_ / BK);   // 96 tiles
    float4 av, wv;

    {
        av = *reinterpret_cast<const float4*>(Aph[0] + (size_t)(bm + arow) * H_ + acv);
        store_a_dup(As2[0], av, arow, acv);
        if (tid < 256) {
            wv = *reinterpret_cast<const float4*>(Wph[0] + (size_t)(bn + wrow) * H_ + wcv);
            store_w(Ws[0], wv, wrow, wcv);
        }
    }
    __syncthreads();

    int p = 0;
    for (int t = 0; t < NT; t++) {
        if (t + 1 < NT) {
            int tn = t + 1;
            int ph = tn >> 5;            // 32 tiles per 512-K phase
            int kt = (tn & 31) * BK;
            av = *reinterpret_cast<const float4*>(Aph[ph] + (size_t)(bm + arow) * H_ + kt + acv);
            if (tid < 256)
                wv = *reinterpret_cast<const float4*>(Wph[ph] + (size_t)(bn + wrow) * H_ + kt + wcv);
        }
        tile_compute(acc2, As2[p], Ws[p], ty, tx);
        if (t + 1 < NT) {
            store_a_dup(As2[p ^ 1], av, arow, acv);
            if (tid < 256) store_w(Ws[p ^ 1], wv, wrow, wcv);
        }
        __syncthreads();
        p ^= 1;
    }

    float4 b1 = *reinterpret_cast<const float4*>(bli + bn + tx * 4);
    float4 b2 = *reinterpret_cast<const float4*>(blt + bn + tx * 4);
    float4 bb = make_float4(b1.x + b2.x, b1.y + b2.y, b1.z + b2.z, b1.w + b2.w);
#pragma unroll
    for (int i = 0; i < 4; i++) {
        float2 c0 = unpk(acc2[i][0]);
        float2 c1 = unpk(acc2[i][1]);
        int r = bm + ty * 4 + i;
        *reinterpret_cast<float4*>(out + (size_t)r * H_ + bn + tx * 4) =
            make_float4(fmaxf(c0.x + bb.x, 0.f), fmaxf(c0.y + bb.y, 0.f),
                        fmaxf(c1.x + bb.z, 0.f), fmaxf(c1.y + bb.w, 0.f));
    }
}

// ---------------------------------------------------------------------------
extern "C" void kernel_launch(void* const* d_in, const int* in_sizes, int n_in,
                              void* d_out, int out_size) {
    (void)in_sizes; (void)n_in; (void)out_size;
    const float* it  = (const float*)d_in[0];
    const float* ii  = (const float*)d_in[1];
    const float* btf = (const float*)d_in[2];
    const float* bif = (const float*)d_in[3];
    const float* Wu  = (const float*)d_in[4];
    const float* bu  = (const float*)d_in[5];
    const float* Wli = (const float*)d_in[6];
    const float* bli = (const float*)d_in[7];
    const float* Wri = (const float*)d_in[8];
    const float* Wlt = (const float*)d_in[9];
    const float* blt = (const float*)d_in[10];
    const float* Wrt = (const float*)d_in[11];
    float* out = (float*)d_out;

    fused_prep<<<1280, 512>>>(it, ii, Wu, bu, bif, btf, Wri, Wrt);
    gemm_out<<<dim3(B_ / BM, H_ / BN), 512>>>(Wli, Wlt, bli, blt, out);
}

// round 10
// speedup vs baseline: 1.6252x; 1.2856x over previous
#include <cuda_runtime.h>

// Problem dims
#define B_  2048
#define M_  128
#define D_  512
#define H_  512
#define KU_ 1024

// GEMM tiling: 128x64 tile, BK=16, 256 threads, 8Mx4N micro-tile, M-packed f32x2
#define BM 128
#define BN 64
#define BK 16
#define AS_LD (BM + 4)   // 132
#define WS_LD (BN + 4)   // 68

typedef unsigned long long u64;
typedef unsigned int u32;

// Scratch + flags (device globals — no allocation allowed)
__device__ float g_mi[B_ * H_];
__device__ float g_mt[B_ * H_];
__device__ float g_u [B_ * H_];
__device__ u32   g_ucnt;
__device__ u32   g_mcnt[16];

// ---------------------------------------------------------------------------
__device__ __forceinline__ u32 ld_acq(const u32* p) {
    u32 v; asm volatile("ld.acquire.gpu.global.u32 %0, [%1];" : "=r"(v) : "l"(p)); return v;
}
__device__ __forceinline__ void red_rel(u32* p) {
    asm volatile("red.release.gpu.global.add.u32 [%0], 1;" :: "l"(p) : "memory");
}
__device__ __forceinline__ void fma2(u64& d, u64 a, u64 b) {
    asm volatile("fma.rn.f32x2 %0, %1, %2, %0;" : "+l"(d) : "l"(a), "l"(b));
}
__device__ __forceinline__ u64 pack2(float x) {
    u64 r; asm("mov.b64 %0, {%1, %1};" : "=l"(r) : "f"(x)); return r;
}
__device__ __forceinline__ float2 unpk(u64 v) {
    float2 r; asm("mov.b64 {%0,%1}, %2;" : "=f"(r.x), "=f"(r.y) : "l"(v)); return r;
}

// ---------------------------------------------------------------------------
// smem stores: A natural [k][m] (transpose from row float4), W natural [k][n]
// ---------------------------------------------------------------------------
__device__ __forceinline__ void sts_a(float (*As)[AS_LD], const float4& v, int row, int cv) {
    As[cv + 0][row] = v.x; As[cv + 1][row] = v.y;
    As[cv + 2][row] = v.z; As[cv + 3][row] = v.w;
}
__device__ __forceinline__ void sts_w(float (*Ws)[WS_LD], const float4& v, int row, int cv) {
    Ws[cv + 0][row] = v.x; Ws[cv + 1][row] = v.y;
    Ws[cv + 2][row] = v.z; Ws[cv + 3][row] = v.w;
}

// Inner: 8M (4 packed pairs) x 4N per thread. ty=m-group(0..15), tx=n-group(0..15)
__device__ __forceinline__ void tile_fma(
    u64 acc[4][4], const float (*As)[AS_LD], const float (*Ws)[WS_LD], int ty, int tx)
{
#pragma unroll
    for (int kk = 0; kk < BK; kk++) {
        const u64* ap = reinterpret_cast<const u64*>(&As[kk][ty * 8]);
        ulonglong2 a01 = *reinterpret_cast<const ulonglong2*>(ap);
        ulonglong2 a23 = *reinterpret_cast<const ulonglong2*>(ap + 2);
        float4 w = *reinterpret_cast<const float4*>(&Ws[kk][tx * 4]);
        u64 a0 = a01.x, a1 = a01.y, a2 = a23.x, a3 = a23.y;
        u64 w0 = pack2(w.x), w1 = pack2(w.y), w2 = pack2(w.z), w3 = pack2(w.w);
        fma2(acc[0][0], a0, w0); fma2(acc[1][0], a1, w0);
        fma2(acc[2][0], a2, w0); fma2(acc[3][0], a3, w0);
        fma2(acc[0][1], a0, w1); fma2(acc[1][1], a1, w1);
        fma2(acc[2][1], a2, w1); fma2(acc[3][1], a3, w1);
        fma2(acc[0][2], a0, w2); fma2(acc[1][2], a1, w2);
        fma2(acc[2][2], a2, w2); fma2(acc[3][2], a3, w2);
        fma2(acc[0][3], a0, w3); fma2(acc[1][3], a1, w3);
        fma2(acc[2][3], a2, w3); fma2(acc[3][3], a3, w3);
    }
}

// Generic pipelined phase: A [rows bm..bm+127, H_-stride], W0(+W1) [rows bn..bn+63]
__device__ __forceinline__ void run_phase(
    u64 acc[4][4],
    const float* __restrict__ A,
    const float* __restrict__ W0, const float* __restrict__ W1,
    float As[2][BK][AS_LD], float Ws[2][BK][WS_LD],
    int bm, int bn, int tid, int ty, int tx)
{
    const int r0  = tid >> 2;
    const int cv  = (tid & 3) << 2;
    const int NT  = H_ / BK;   // 32

    float4 a0, a1, wv;
    {
        a0 = *reinterpret_cast<const float4*>(A + (size_t)(bm + r0) * H_ + cv);
        a1 = *reinterpret_cast<const float4*>(A + (size_t)(bm + r0 + 64) * H_ + cv);
        wv = *reinterpret_cast<const float4*>(W0 + (size_t)(bn + r0 % 64) * H_ + cv);
        // note: r0 in [0,63] for W since tid<256 -> tid>>2 in [0,63]
        if (W1) {
            float4 w2 = *reinterpret_cast<const float4*>(W1 + (size_t)(bn + r0 % 64) * H_ + cv);
            wv.x += w2.x; wv.y += w2.y; wv.z += w2.z; wv.w += w2.w;
        }
        sts_a(As[0], a0, r0, cv); sts_a(As[0], a1, r0 + 64, cv);
        sts_w(Ws[0], wv, r0 % 64, cv);
    }
    __syncthreads();

    int p = 0;
    for (int t = 0; t < NT; t++) {
        if (t + 1 < NT) {
            int kt = (t + 1) * BK;
            a0 = *reinterpret_cast<const float4*>(A + (size_t)(bm + r0) * H_ + kt + cv);
            a1 = *reinterpret_cast<const float4*>(A + (size_t)(bm + r0 + 64) * H_ + kt + cv);
            wv = *reinterpret_cast<const float4*>(W0 + (size_t)(bn + r0 % 64) * H_ + kt + cv);
            if (W1) {
                float4 w2 = *reinterpret_cast<const float4*>(W1 + (size_t)(bn + r0 % 64) * H_ + kt + cv);
                wv.x += w2.x; wv.y += w2.y; wv.z += w2.z; wv.w += w2.w;
            }
        }
        tile_fma(acc, As[p], Ws[p], ty, tx);
        if (t + 1 < NT) {
            sts_a(As[p ^ 1], a0, r0, cv); sts_a(As[p ^ 1], a1, r0 + 64, cv);
            sts_w(Ws[p ^ 1], wv, r0 % 64, cv);
        }
        __syncthreads();
        p ^= 1;
    }
}

// ---------------------------------------------------------------------------
// Flag reset (runs before main kernel every replay)
// ---------------------------------------------------------------------------
__global__ void zero_flags() {
    if (threadIdx.x == 0) g_ucnt = 0;
    if (threadIdx.x < 16) g_mcnt[threadIdx.x] = 0;
}

// ---------------------------------------------------------------------------
// Main fused kernel. grid=256, 256 threads, occupancy>=2 forced -> all CTAs
// co-resident (296 slots >= 256), so flag spins cannot deadlock.
//   CTAs 0..127   : compute (gemm_user tile -> phase3 -> phases 1,2 -> out)
//   CTAs 128..255 : mean workers (8 per m-tile), release per-tile counters
// ---------------------------------------------------------------------------
__global__ void __launch_bounds__(256, 2) fused_all(
    const float* __restrict__ it,  const float* __restrict__ ii,
    const float* __restrict__ btf, const float* __restrict__ bif,
    const float* __restrict__ Wu,  const float* __restrict__ bu,
    const float* __restrict__ Wli, const float* __restrict__ bli,
    const float* __restrict__ Wri, const float* __restrict__ Wlt,
    const float* __restrict__ blt, const float* __restrict__ Wrt,
    float* __restrict__ out)
{
    __shared__ float As[2][BK][AS_LD];
    __shared__ float Ws[2][BK][WS_LD];

    const int cid = blockIdx.x;
    const int tid = threadIdx.x;

    if (cid >= 128) {
        // ================= mean workers =================
        int w = cid - 128;            // 0..127
        int t = w >> 3;               // m-tile 0..15
        int k = w & 7;                // worker-in-tile
        int modal = k >> 2;           // 0: img, 1: txt
        int bstart = t * 128 + (k & 3) * 32;
        const float* src = modal ? btf : bif;
        float*       dst = modal ? g_mt : g_mi;

        const int col = tid & 127;
        for (int itn = 0; itn < 16; itn++) {
            int b = bstart + itn * 2 + (tid >> 7);
            const float4* q = reinterpret_cast<const float4*>(src)
                              + (size_t)b * (M_ * H_ / 4) + col;
            float4 acc = make_float4(0.f, 0.f, 0.f, 0.f);
#pragma unroll 8
            for (int m = 0; m < M_; m++) {
                float4 v = q[(size_t)m * (H_ / 4)];
                acc.x += v.x; acc.y += v.y; acc.z += v.z; acc.w += v.w;
            }
            const float s = 1.0f / (float)M_;
            reinterpret_cast<float4*>(dst)[(size_t)b * (H_ / 4) + col] =
                make_float4(acc.x * s, acc.y * s, acc.z * s, acc.w * s);
        }
        __syncthreads();
        if (tid == 0) red_rel(&g_mcnt[t]);
        return;
    }

    // ================= compute CTAs =================
    const int bm = (cid >> 3) * BM;   // 16 m-tiles
    const int bn = (cid & 7) * BN;    // 8 n-tiles
    const int tx = tid & 15;
    const int ty = tid >> 4;
    const int r0 = tid >> 2;
    const int cv = (tid & 3) << 2;

    // ---- Stage 1: gemm_user tile: u = concat(it,ii) @ Wu^T + bu ----
    {
        u64 acc[4][4];
#pragma unroll
        for (int i = 0; i < 4; i++)
#pragma unroll
            for (int j = 0; j < 4; j++) acc[i][j] = 0ull;

        const int NT = KU_ / BK;   // 64
        float4 a0, a1, wv;
        {
            int kg = cv;
            const float* s0 = (kg < D_) ? (it + (size_t)(bm + r0) * D_ + kg)
                                        : (ii + (size_t)(bm + r0) * D_ + (kg - D_));
            const float* s1 = (kg < D_) ? (it + (size_t)(bm + r0 + 64) * D_ + kg)
                                        : (ii + (size_t)(bm + r0 + 64) * D_ + (kg - D_));
            a0 = *reinterpret_cast<const float4*>(s0);
            a1 = *reinterpret_cast<const float4*>(s1);
            wv = *reinterpret_cast<const float4*>(Wu + (size_t)(bn + (r0 & 63)) * KU_ + cv);
            sts_a(As[0], a0, r0, cv); sts_a(As[0], a1, r0 + 64, cv);
            sts_w(Ws[0], wv, r0 & 63, cv);
        }
        __syncthreads();

        int p = 0;
        for (int t = 0; t < NT; t++) {
            if (t + 1 < NT) {
                int kt = (t + 1) * BK;
                int kg = kt + cv;
                const float* s0 = (kg < D_) ? (it + (size_t)(bm + r0) * D_ + kg)
                                            : (ii + (size_t)(bm + r0) * D_ + (kg - D_));
                const float* s1 = (kg < D_) ? (it + (size_t)(bm + r0 + 64) * D_ + kg)
                                            : (ii + (size_t)(bm + r0 + 64) * D_ + (kg - D_));
                a0 = *reinterpret_cast<const float4*>(s0);
                a1 = *reinterpret_cast<const float4*>(s1);
                wv = *reinterpret_cast<const float4*>(Wu + (size_t)(bn + (r0 & 63)) * KU_ + kt + cv);
            }
            tile_fma(acc, As[p], Ws[p], ty, tx);
            if (t + 1 < NT) {
                sts_a(As[p ^ 1], a0, r0, cv); sts_a(As[p ^ 1], a1, r0 + 64, cv);
                sts_w(Ws[p ^ 1], wv, r0 & 63, cv);
            }
            __syncthreads();
            p ^= 1;
        }

        // epilogue: + bu -> g_u
        float4 bb = *reinterpret_cast<const float4*>(bu + bn + tx * 4);
#pragma unroll
        for (int i = 0; i < 4; i++) {
            float2 c0 = unpk(acc[i][0]);
            float2 c1 = unpk(acc[i][1]);
            float2 c2 = unpk(acc[i][2]);
            float2 c3 = unpk(acc[i][3]);
            int r = bm + ty * 8 + 2 * i;
            *reinterpret_cast<float4*>(g_u + (size_t)r * H_ + bn + tx * 4) =
                make_float4(c0.x + bb.x, c1.x + bb.y, c2.x + bb.z, c3.x + bb.w);
            *reinterpret_cast<float4*>(g_u + (size_t)(r + 1) * H_ + bn + tx * 4) =
                make_float4(c0.y + bb.x, c1.y + bb.y, c2.y + bb.z, c3.y + bb.w);
        }
    }
    __syncthreads();
    if (tid == 0) red_rel(&g_ucnt);

    // ---- wait for full g_u ----
    if (tid == 0) { while (ld_acq(&g_ucnt) < 128u) __nanosleep(128); }
    __syncthreads();

    // ---- Stage 2: out accumulation ----
    u64 acc[4][4];
#pragma unroll
    for (int i = 0; i < 4; i++)
#pragma unroll
        for (int j = 0; j < 4; j++) acc[i][j] = 0ull;

    // phase 3 first (only needs g_u); W = Wri + Wrt folded at load
    run_phase(acc, g_u, Wri, Wrt, As, Ws, bm, bn, tid, ty, tx);

    // wait for this m-tile's means
    if (tid == 0) { while (ld_acq(&g_mcnt[bm >> 7]) < 8u) __nanosleep(128); }
    __syncthreads();

    run_phase(acc, g_mi, Wli, (const float*)0, As, Ws, bm, bn, tid, ty, tx);
    run_phase(acc, g_mt, Wlt, (const float*)0, As, Ws, bm, bn, tid, ty, tx);

    // epilogue: + (bli+blt), ReLU
    float4 b1 = *reinterpret_cast<const float4*>(bli + bn + tx * 4);
    float4 b2 = *reinterpret_cast<const float4*>(blt + bn + tx * 4);
    float4 bb = make_float4(b1.x + b2.x, b1.y + b2.y, b1.z + b2.z, b1.w + b2.w);
#pragma unroll
    for (int i = 0; i < 4; i++) {
        float2 c0 = unpk(acc[i][0]);
        float2 c1 = unpk(acc[i][1]);
        float2 c2 = unpk(acc[i][2]);
        float2 c3 = unpk(acc[i][3]);
        int r = bm + ty * 8 + 2 * i;
        *reinterpret_cast<float4*>(out + (size_t)r * H_ + bn + tx * 4) =
            make_float4(fmaxf(c0.x + bb.x, 0.f), fmaxf(c1.x + bb.y, 0.f),
                        fmaxf(c2.x + bb.z, 0.f), fmaxf(c3.x + bb.w, 0.f));
        *reinterpret_cast<float4*>(out + (size_t)(r + 1) * H_ + bn + tx * 4) =
            make_float4(fmaxf(c0.y + bb.x, 0.f), fmaxf(c1.y + bb.y, 0.f),
                        fmaxf(c2.y + bb.z, 0.f), fmaxf(c3.y + bb.w, 0.f));
    }
}

// ---------------------------------------------------------------------------
extern "C" void kernel_launch(void* const* d_in, const int* in_sizes, int n_in,
                              void* d_out, int out_size) {
    (void)in_sizes; (void)n_in; (void)out_size;
    const float* it  = (const float*)d_in[0];
    const float* ii  = (const float*)d_in[1];
    const float* btf = (const float*)d_in[2];
    const float* bif = (const float*)d_in[3];
    const float* Wu  = (const float*)d_in[4];
    const float* bu  = (const float*)d_in[5];
    const float* Wli = (const float*)d_in[6];
    const float* bli = (const float*)d_in[7];
    const float* Wri = (const float*)d_in[8];
    const float* Wlt = (const float*)d_in[9];
    const float* blt = (const float*)d_in[10];
    const float* Wrt = (const float*)d_in[11];
    float* out = (float*)d_out;

    zero_flags<<<1, 32>>>();
    fused_all<<<256, 256>>>(it, ii, btf, bif, Wu, bu, Wli, bli, Wri,
                            Wlt, blt, Wrt, out);
}